// round 11
// baseline (speedup 1.0000x reference)
#include <cuda_runtime.h>
#include <cstdint>
#include <cstddef>

// TensorFusion: B=32, N=4096, C=16, D=256
//   out[b,c,d]  = (1/N) * sum_n [r[b,n,c] >= 0.5] * v[b,n,d]        c in 0..15
//   out[b,16,d] = (1/N) * sum_n [all c: r[b,n,c] < 0.5] * v[b,n,d]

#define B_DIM 32
#define N_DIM 4096
#define C_DIM 16
#define D_DIM 256
#define OUT_C (C_DIM + 1)

#define SPLIT 16
#define NCHUNK (N_DIM / SPLIT)     // 256 rows per CTA
#define THREADS 256
#define NGROUPS 4
#define RPG (NCHUNK / NGROUPS)     // 64 rows per n-group
#define C_PAD 18                   // 17 mask pairs, padded (16B-aligned rows)

__global__ void tf_zero_kernel(float* __restrict__ out, int n) {
    int i = blockIdx.x * blockDim.x + threadIdx.x;
    if (i < n) out[i] = 0.0f;
}

// Packed f32x2 FMA: acc.{lo,hi} += m.{lo,hi} * v.{lo,hi}  (one FFMA2, fma pipe)
#define FMA2(acc, m, vv) \
    asm("fma.rn.f32x2 %0, %1, %2, %0;" : "+l"(acc) : "l"(m), "l"(vv))

__global__ __launch_bounds__(THREADS, 2)
void tf_fusion_kernel(const float* __restrict__ r,
                      const float* __restrict__ v,
                      float* __restrict__ out) {
    // Mask floats, duplicated into f32x2 pairs: maskd[row][c] = (m, m)
    __shared__ __align__(16) unsigned long long maskd[NCHUNK][C_PAD];  // 36.9 KB
    __shared__ __align__(16) float red[OUT_C][D_DIM];                  // 17.4 KB

    const int b  = blockIdx.y;
    const int n0 = blockIdx.x * NCHUNK;
    const int t  = threadIdx.x;
    const int g  = t >> 6;        // n-group 0..3
    const int q  = t & 63;        // d-quad index (owns d = 4q..4q+3)

    // ---- Phase A: 17 mask floats (0.0/1.0) per row, stored as dup pairs ----
    {
        const float4* rp = reinterpret_cast<const float4*>(
            r + (size_t)(b * N_DIM + n0 + t) * C_DIM);
        unsigned m = 0u;
        #pragma unroll
        for (int j = 0; j < 4; ++j) {
            float4 x = rp[j];
            m |= (x.x >= 0.5f ? 1u : 0u) << (4 * j + 0);
            m |= (x.y >= 0.5f ? 1u : 0u) << (4 * j + 1);
            m |= (x.z >= 0.5f ? 1u : 0u) << (4 * j + 2);
            m |= (x.w >= 0.5f ? 1u : 0u) << (4 * j + 3);
        }
        if (m == 0u) m = 1u << 16;   // special channel: no category matched
        #pragma unroll
        for (int c = 0; c < OUT_C; ++c) {
            unsigned u = ((m >> c) & 1u) ? 0x3f800000u : 0u;  // 1.0f or 0.0f
            maskd[t][c] = (unsigned long long)u | ((unsigned long long)u << 32);
        }
    }
    __syncthreads();

    // ---- Phase B: group g streams its 64 rows; thread owns 4 d-columns ----
    // Software-pipelined: prefetch 4 rows (buffer B/A) while FMAing 4 rows.
    unsigned long long a0[OUT_C], a1[OUT_C];
    #pragma unroll
    for (int c = 0; c < OUT_C; ++c) { a0[c] = 0ull; a1[c] = 0ull; }

    // v row = 256 floats = 64 x 16B; thread reads 16B at quad q.
    const ulonglong2* vp = reinterpret_cast<const ulonglong2*>(
        v + (size_t)(b * N_DIM + n0 + g * RPG) * D_DIM) + q;
    const unsigned long long* mbase = &maskd[g * RPG][0];

    #define VROW(row) vp[(size_t)(row) * (D_DIM / 4)]

    // FMA one 4-row batch against its mask quad
    #define FMA_BATCH(X0, X1, X2, X3, I)                                      \
    do {                                                                      \
        _Pragma("unroll")                                                     \
        for (int j = 0; j < 4; ++j) {                                         \
            const ulonglong2 xv = (j == 0) ? (X0) : (j == 1) ? (X1)           \
                                : (j == 2) ? (X2) : (X3);                     \
            const unsigned long long* mrow = mbase + (size_t)((I) + j) * C_PAD;\
            _Pragma("unroll")                                                 \
            for (int c = 0; c < C_DIM; c += 2) {                              \
                ulonglong2 mm = *reinterpret_cast<const ulonglong2*>(mrow + c);\
                FMA2(a0[c],     mm.x, xv.x);                                  \
                FMA2(a1[c],     mm.x, xv.y);                                  \
                FMA2(a0[c + 1], mm.y, xv.x);                                  \
                FMA2(a1[c + 1], mm.y, xv.y);                                  \
            }                                                                 \
            unsigned long long m16 = mrow[16];                                \
            FMA2(a0[16], m16, xv.x);                                          \
            FMA2(a1[16], m16, xv.y);                                          \
        }                                                                     \
    } while (0)

    // Prologue: fill buffer A with rows 0..3
    ulonglong2 A0 = VROW(0), A1 = VROW(1), A2 = VROW(2), A3 = VROW(3);

    #pragma unroll 1
    for (int i = 0; i < RPG; i += 8) {
        // Prefetch rows i+4..i+7 into buffer B, then consume A.
        ulonglong2 B0 = VROW(i + 4), B1 = VROW(i + 5),
                   B2 = VROW(i + 6), B3 = VROW(i + 7);
        FMA_BATCH(A0, A1, A2, A3, i);
        // Prefetch rows i+8..i+11 (wrapped on last iter; rows 0..3 reloaded
        // into A but never consumed), then consume B.
        A0 = VROW((i + 8)  & (RPG - 1));
        A1 = VROW((i + 9)  & (RPG - 1));
        A2 = VROW((i + 10) & (RPG - 1));
        A3 = VROW((i + 11) & (RPG - 1));
        FMA_BATCH(B0, B1, B2, B3, i + 4);
    }
    __syncthreads();   // maskd no longer needed; red takes over

    // ---- Phase C1: reduce the 4 n-groups through shared memory ----
    #pragma unroll 1
    for (int gg = 0; gg < NGROUPS; ++gg) {
        if (g == gg) {
            #pragma unroll
            for (int c = 0; c < OUT_C; ++c) {
                float2 lo = *reinterpret_cast<float2*>(&a0[c]);
                float2 hi = *reinterpret_cast<float2*>(&a1[c]);
                float4* dst = reinterpret_cast<float4*>(&red[c][q * 4]);
                if (gg == 0) {
                    *dst = make_float4(lo.x, lo.y, hi.x, hi.y);
                } else {
                    float4 p = *dst;
                    *dst = make_float4(p.x + lo.x, p.y + lo.y,
                                       p.z + hi.x, p.w + hi.y);
                }
            }
        }
        __syncthreads();
    }

    // ---- Phase C2: scale + one atomic pass (256 threads cover D) ----
    const float scale = 1.0f / (float)N_DIM;
    float* op = out + (size_t)b * OUT_C * D_DIM + t;
    #pragma unroll
    for (int c = 0; c < OUT_C; ++c) {
        atomicAdd(op + c * D_DIM, red[c][t] * scale);
    }
}

extern "C" void kernel_launch(void* const* d_in, const int* in_sizes, int n_in,
                              void* d_out, int out_size) {
    // Inputs per metadata order: r_tensor (B*N*C), v_tensor (B*N*D).
    // Disambiguate defensively by element count.
    const float* r = (const float*)d_in[0];
    const float* v = (const float*)d_in[1];
    if (n_in >= 2 && in_sizes[0] == B_DIM * N_DIM * D_DIM &&
        in_sizes[1] == B_DIM * N_DIM * C_DIM) {
        r = (const float*)d_in[1];
        v = (const float*)d_in[0];
    }
    float* out = (float*)d_out;

    const int out_elems = B_DIM * OUT_C * D_DIM;  // 139264
    tf_zero_kernel<<<(out_elems + 255) / 256, 256>>>(out, out_elems);

    dim3 grid(SPLIT, B_DIM);
    tf_fusion_kernel<<<grid, THREADS>>>(r, v, out);
}

// round 12
// speedup vs baseline: 1.1796x; 1.1796x over previous
#include <cuda_runtime.h>
#include <cstdint>
#include <cstddef>

// TensorFusion: B=32, N=4096, C=16, D=256
//   out[b,c,d]  = (1/N) * sum_n [r[b,n,c] >= 0.5] * v[b,n,d]        c in 0..15
//   out[b,16,d] = (1/N) * sum_n [all c: r[b,n,c] < 0.5] * v[b,n,d]

#define B_DIM 32
#define N_DIM 4096
#define C_DIM 16
#define D_DIM 256
#define OUT_C (C_DIM + 1)

#define SPLIT 16
#define NCHUNK (N_DIM / SPLIT)     // 256 rows per CTA
#define THREADS 256
#define NG 2                       // n-groups per CTA
#define RPG2 (NCHUNK / NG)         // 128 rows per n-group
#define C_PAD 18                   // 17 mask pairs padded (16B-aligned rows)

__global__ void tf_zero_kernel(float* __restrict__ out, int n) {
    int i = blockIdx.x * blockDim.x + threadIdx.x;
    if (i < n) out[i] = 0.0f;
}

// Packed f32x2 FMA: acc.{lo,hi} += m.{lo,hi} * v.{lo,hi}  (one FFMA2, fma pipe)
#define FMA2(acc, m, vv) \
    asm("fma.rn.f32x2 %0, %1, %2, %0;" : "+l"(acc) : "l"(m), "l"(vv))

// One row x CCNT channels: LDS.128 mask pairs + 2 FFMA2 per channel.
template<int CBASE, int CCNT>
__device__ __forceinline__ void fma_row(const unsigned long long* __restrict__ mrow,
                                        ulonglong2 xv,
                                        unsigned long long* __restrict__ acc0,
                                        unsigned long long* __restrict__ acc1) {
    #pragma unroll
    for (int k = 0; k + 1 < CCNT; k += 2) {
        ulonglong2 mm = *reinterpret_cast<const ulonglong2*>(mrow + CBASE + k);
        FMA2(acc0[k],     mm.x, xv.x);
        FMA2(acc1[k],     mm.x, xv.y);
        FMA2(acc0[k + 1], mm.y, xv.x);
        FMA2(acc1[k + 1], mm.y, xv.y);
    }
    if (CCNT & 1) {
        unsigned long long m = mrow[CBASE + CCNT - 1];
        FMA2(acc0[CCNT - 1], m, xv.x);
        FMA2(acc1[CCNT - 1], m, xv.y);
    }
}

// Stream RPG2 rows with a 2-row-deep register prefetch pipeline.
template<int CBASE, int CCNT>
__device__ __forceinline__ void stream_rows(const ulonglong2* __restrict__ vp,
                                            const unsigned long long* __restrict__ mbase,
                                            unsigned long long* __restrict__ acc0,
                                            unsigned long long* __restrict__ acc1) {
    ulonglong2 A0 = vp[0 * (D_DIM / 4)];
    ulonglong2 A1 = vp[1 * (D_DIM / 4)];
    #pragma unroll 1
    for (int i = 0; i < RPG2; i += 4) {
        ulonglong2 B0 = vp[(size_t)(i + 2) * (D_DIM / 4)];
        ulonglong2 B1 = vp[(size_t)(i + 3) * (D_DIM / 4)];
        fma_row<CBASE, CCNT>(mbase + (size_t)(i + 0) * C_PAD, A0, acc0, acc1);
        fma_row<CBASE, CCNT>(mbase + (size_t)(i + 1) * C_PAD, A1, acc0, acc1);
        A0 = vp[(size_t)((i + 4) & (RPG2 - 1)) * (D_DIM / 4)];
        A1 = vp[(size_t)((i + 5) & (RPG2 - 1)) * (D_DIM / 4)];
        fma_row<CBASE, CCNT>(mbase + (size_t)(i + 2) * C_PAD, B0, acc0, acc1);
        fma_row<CBASE, CCNT>(mbase + (size_t)(i + 3) * C_PAD, B1, acc0, acc1);
    }
}

// Reduction write/add for this thread's channel slice.
template<int CBASE, int CCNT>
__device__ __forceinline__ void reduce_write(int first,
                                             const unsigned long long* __restrict__ acc0,
                                             const unsigned long long* __restrict__ acc1,
                                             float red[OUT_C][D_DIM], int q) {
    #pragma unroll
    for (int k = 0; k < CCNT; ++k) {
        float2 lo = *reinterpret_cast<const float2*>(&acc0[k]);
        float2 hi = *reinterpret_cast<const float2*>(&acc1[k]);
        float4* dst = reinterpret_cast<float4*>(&red[CBASE + k][q * 4]);
        if (first) {
            *dst = make_float4(lo.x, lo.y, hi.x, hi.y);
        } else {
            float4 p = *dst;
            *dst = make_float4(p.x + lo.x, p.y + lo.y, p.z + hi.x, p.w + hi.y);
        }
    }
}

__global__ __launch_bounds__(THREADS, 3)
void tf_fusion_kernel(const float* __restrict__ r,
                      const float* __restrict__ v,
                      float* __restrict__ out) {
    // Mask floats, duplicated into f32x2 pairs: maskd[row][c] = (m, m)
    __shared__ __align__(16) unsigned long long maskd[NCHUNK][C_PAD];  // 36.9 KB
    __shared__ __align__(16) float red[OUT_C][D_DIM];                  // 17.4 KB

    const int b  = blockIdx.y;
    const int n0 = blockIdx.x * NCHUNK;
    const int t  = threadIdx.x;
    const int q  = t & 63;         // d-quad index (owns d = 4q..4q+3)
    const int ch = (t >> 6) & 1;   // channel half: 0 -> c 0..7, 1 -> c 8..16
    const int ng = (t >> 7) & 1;   // n-group (128 rows each)

    // ---- Phase A: 17 mask floats (0.0/1.0) per row, stored as dup pairs ----
    {
        const float4* rp = reinterpret_cast<const float4*>(
            r + (size_t)(b * N_DIM + n0 + t) * C_DIM);
        unsigned m = 0u;
        #pragma unroll
        for (int j = 0; j < 4; ++j) {
            float4 x = rp[j];
            m |= (x.x >= 0.5f ? 1u : 0u) << (4 * j + 0);
            m |= (x.y >= 0.5f ? 1u : 0u) << (4 * j + 1);
            m |= (x.z >= 0.5f ? 1u : 0u) << (4 * j + 2);
            m |= (x.w >= 0.5f ? 1u : 0u) << (4 * j + 3);
        }
        if (m == 0u) m = 1u << 16;   // special channel: no category matched
        #pragma unroll
        for (int c = 0; c < OUT_C; ++c) {
            unsigned u = ((m >> c) & 1u) ? 0x3f800000u : 0u;  // 1.0f or 0.0f
            maskd[t][c] = (unsigned long long)u | ((unsigned long long)u << 32);
        }
    }
    __syncthreads();

    // ---- Phase B: thread streams its 128 rows for its channel half ----
    unsigned long long acc0[9], acc1[9];   // <= 9 channels x (2 f32x2)
    #pragma unroll
    for (int k = 0; k < 9; ++k) { acc0[k] = 0ull; acc1[k] = 0ull; }

    const ulonglong2* vp = reinterpret_cast<const ulonglong2*>(
        v + (size_t)(b * N_DIM + n0 + ng * RPG2) * D_DIM) + q;
    const unsigned long long* mbase = &maskd[ng * RPG2][0];

    if (ch == 0) {
        stream_rows<0, 8>(vp, mbase, acc0, acc1);
    } else {
        stream_rows<8, 9>(vp, mbase, acc0, acc1);
    }
    __syncthreads();   // all mask reads done before red rounds begin

    // ---- Phase C1: reduce the 2 n-groups through shared memory ----
    #pragma unroll 1
    for (int gg = 0; gg < NG; ++gg) {
        if (ng == gg) {
            if (ch == 0) reduce_write<0, 8>(gg == 0, acc0, acc1, red, q);
            else         reduce_write<8, 9>(gg == 0, acc0, acc1, red, q);
        }
        __syncthreads();
    }

    // ---- Phase C2: scale + one atomic pass (256 threads cover D) ----
    const float scale = 1.0f / (float)N_DIM;
    float* op = out + (size_t)b * OUT_C * D_DIM + t;
    #pragma unroll
    for (int c = 0; c < OUT_C; ++c) {
        atomicAdd(op + c * D_DIM, red[c][t] * scale);
    }
}

extern "C" void kernel_launch(void* const* d_in, const int* in_sizes, int n_in,
                              void* d_out, int out_size) {
    // Inputs per metadata order: r_tensor (B*N*C), v_tensor (B*N*D).
    // Disambiguate defensively by element count.
    const float* r = (const float*)d_in[0];
    const float* v = (const float*)d_in[1];
    if (n_in >= 2 && in_sizes[0] == B_DIM * N_DIM * D_DIM &&
        in_sizes[1] == B_DIM * N_DIM * C_DIM) {
        r = (const float*)d_in[1];
        v = (const float*)d_in[0];
    }
    float* out = (float*)d_out;

    const int out_elems = B_DIM * OUT_C * D_DIM;  // 139264
    tf_zero_kernel<<<(out_elems + 255) / 256, 256>>>(out, out_elems);

    dim3 grid(SPLIT, B_DIM);
    tf_fusion_kernel<<<grid, THREADS>>>(r, v, out);
}

// round 13
// speedup vs baseline: 1.1815x; 1.0017x over previous
#include <cuda_runtime.h>
#include <cstdint>
#include <cstddef>

// TensorFusion: B=32, N=4096, C=16, D=256
//   out[b,c,d]  = (1/N) * sum_n [r[b,n,c] >= 0.5] * v[b,n,d]        c in 0..15
//   out[b,16,d] = (1/N) * sum_n [all c: r[b,n,c] < 0.5] * v[b,n,d]

#define B_DIM 32
#define N_DIM 4096
#define C_DIM 16
#define D_DIM 256
#define OUT_C (C_DIM + 1)

#define SPLIT 16
#define NCHUNK (N_DIM / SPLIT)     // 256 rows per CTA
#define THREADS 256
#define NG 2                       // n-groups per CTA
#define RPG2 (NCHUNK / NG)         // 128 rows per n-group
#define C_PAD 18                   // 17 mask pairs padded (16B-aligned rows)

#define S_STAGES 4                 // cp.async ring depth
#define RSTAGE 4                   // rows per stage per n-group
#define STAGE_ITERS (RPG2 / RSTAGE)   // 32
#define ROW_BYTES (D_DIM * 4)      // 1 KB per v row

#define MASKD_BYTES (NCHUNK * C_PAD * 8)                    // 36864
#define POOL_BYTES  (S_STAGES * NG * RSTAGE * ROW_BYTES)    // 32768 (>= red 17408)
#define SMEM_TOTAL  (MASKD_BYTES + POOL_BYTES)              // 69632

__global__ void tf_zero_kernel(float* __restrict__ out, int n) {
    int i = blockIdx.x * blockDim.x + threadIdx.x;
    if (i < n) out[i] = 0.0f;
}

// Packed f32x2 FMA: acc.{lo,hi} += m.{lo,hi} * v.{lo,hi}  (one FFMA2, fma pipe)
#define FMA2(acc, m, vv) \
    asm("fma.rn.f32x2 %0, %1, %2, %0;" : "+l"(acc) : "l"(m), "l"(vv))

__device__ __forceinline__ void cp_async16(uint32_t dst_smem, const void* src) {
    asm volatile("cp.async.cg.shared.global [%0], [%1], 16;"
                 :: "r"(dst_smem), "l"(src));
}
#define CP_COMMIT() asm volatile("cp.async.commit_group;" ::: "memory")
#define CP_WAIT3()  asm volatile("cp.async.wait_group 3;" ::: "memory")

// One row x CCNT channels: LDS.128 mask pairs + 2 FFMA2 per channel.
template<int CBASE, int CCNT>
__device__ __forceinline__ void fma_row(const unsigned long long* __restrict__ mrow,
                                        ulonglong2 xv,
                                        unsigned long long* __restrict__ acc0,
                                        unsigned long long* __restrict__ acc1) {
    #pragma unroll
    for (int k = 0; k + 1 < CCNT; k += 2) {
        ulonglong2 mm = *reinterpret_cast<const ulonglong2*>(mrow + CBASE + k);
        FMA2(acc0[k],     mm.x, xv.x);
        FMA2(acc1[k],     mm.x, xv.y);
        FMA2(acc0[k + 1], mm.y, xv.x);
        FMA2(acc1[k + 1], mm.y, xv.y);
    }
    if (CCNT & 1) {
        unsigned long long m = mrow[CBASE + CCNT - 1];
        FMA2(acc0[CCNT - 1], m, xv.x);
        FMA2(acc1[CCNT - 1], m, xv.y);
    }
}

// Consume one staged 4-row block for this thread's channel slice.
template<int CBASE, int CCNT>
__device__ __forceinline__ void consume_stage(const char* __restrict__ vs,
                                              const unsigned long long* __restrict__ mrow0,
                                              unsigned long long* __restrict__ acc0,
                                              unsigned long long* __restrict__ acc1) {
    // Batch the 4 LDS.128 of v up front (hide LDS latency), then FMA.
    ulonglong2 x0 = *reinterpret_cast<const ulonglong2*>(vs + 0 * ROW_BYTES);
    ulonglong2 x1 = *reinterpret_cast<const ulonglong2*>(vs + 1 * ROW_BYTES);
    ulonglong2 x2 = *reinterpret_cast<const ulonglong2*>(vs + 2 * ROW_BYTES);
    ulonglong2 x3 = *reinterpret_cast<const ulonglong2*>(vs + 3 * ROW_BYTES);
    fma_row<CBASE, CCNT>(mrow0 + 0 * C_PAD, x0, acc0, acc1);
    fma_row<CBASE, CCNT>(mrow0 + 1 * C_PAD, x1, acc0, acc1);
    fma_row<CBASE, CCNT>(mrow0 + 2 * C_PAD, x2, acc0, acc1);
    fma_row<CBASE, CCNT>(mrow0 + 3 * C_PAD, x3, acc0, acc1);
}

// Reduction write/add for this thread's channel slice.
template<int CBASE, int CCNT>
__device__ __forceinline__ void reduce_write(int first,
                                             const unsigned long long* __restrict__ acc0,
                                             const unsigned long long* __restrict__ acc1,
                                             float (*red)[D_DIM], int q) {
    #pragma unroll
    for (int k = 0; k < CCNT; ++k) {
        float2 lo = *reinterpret_cast<const float2*>(&acc0[k]);
        float2 hi = *reinterpret_cast<const float2*>(&acc1[k]);
        float4* dst = reinterpret_cast<float4*>(&red[CBASE + k][q * 4]);
        if (first) {
            *dst = make_float4(lo.x, lo.y, hi.x, hi.y);
        } else {
            float4 p = *dst;
            *dst = make_float4(p.x + lo.x, p.y + lo.y, p.z + hi.x, p.w + hi.y);
        }
    }
}

extern __shared__ __align__(16) char dynsmem[];

__global__ __launch_bounds__(THREADS, 3)
void tf_fusion_kernel(const float* __restrict__ r,
                      const float* __restrict__ v,
                      float* __restrict__ out) {
    // Layout: [maskd: NCHUNK x C_PAD ull][pool: stage ring, reused as red[]]
    unsigned long long* maskd = reinterpret_cast<unsigned long long*>(dynsmem);
    char* pool = dynsmem + MASKD_BYTES;

    const int b  = blockIdx.y;
    const int n0 = blockIdx.x * NCHUNK;
    const int t  = threadIdx.x;
    const int q  = t & 63;         // d-quad index (owns d = 4q..4q+3)
    const int ch = (t >> 6) & 1;   // channel half: 0 -> c 0..7, 1 -> c 8..16
    const int ng = (t >> 7) & 1;   // n-group (128 rows each)

    uint32_t pool_u32;
    asm("{ .reg .u64 tt; cvta.to.shared.u64 tt, %1; cvt.u32.u64 %0, tt; }"
        : "=r"(pool_u32) : "l"(pool));

    // ---- Phase A: 17 mask floats (0.0/1.0) per row, stored as dup pairs ----
    {
        const float4* rp = reinterpret_cast<const float4*>(
            r + (size_t)(b * N_DIM + n0 + t) * C_DIM);
        unsigned m = 0u;
        #pragma unroll
        for (int j = 0; j < 4; ++j) {
            float4 x = rp[j];
            m |= (x.x >= 0.5f ? 1u : 0u) << (4 * j + 0);
            m |= (x.y >= 0.5f ? 1u : 0u) << (4 * j + 1);
            m |= (x.z >= 0.5f ? 1u : 0u) << (4 * j + 2);
            m |= (x.w >= 0.5f ? 1u : 0u) << (4 * j + 3);
        }
        if (m == 0u) m = 1u << 16;   // special channel: no category matched
        #pragma unroll
        for (int c = 0; c < OUT_C; ++c) {
            unsigned u = ((m >> c) & 1u) ? 0x3f800000u : 0u;  // 1.0f or 0.0f
            maskd[(size_t)t * C_PAD + c] =
                (unsigned long long)u | ((unsigned long long)u << 32);
        }
    }

    // ---- cp.async stage issue: thread t copies 2 x 16B per stage ----
    // chunk (ngc, row = (t>>6)&3, quad = t&63) for ngc in {0,1}
    const int crow  = (t >> 6) & 3;
    const int cquad = t & 63;
    const float* gsrc0 = v + (size_t)(b * N_DIM + n0 + 0 * RPG2 + crow) * D_DIM
                           + cquad * 4;
    const float* gsrc1 = v + (size_t)(b * N_DIM + n0 + 1 * RPG2 + crow) * D_DIM
                           + cquad * 4;
    const uint32_t sdst0 = pool_u32 + (uint32_t)((0 * RSTAGE + crow) * ROW_BYTES
                                                 + cquad * 16);
    const uint32_t sdst1 = pool_u32 + (uint32_t)((1 * RSTAGE + crow) * ROW_BYTES
                                                 + cquad * 16);
    #define ISSUE_STAGE(s)                                                     \
    do {                                                                       \
        int _slot = (s) & (S_STAGES - 1);                                      \
        size_t _goff = (size_t)((s) * RSTAGE) * D_DIM;                         \
        uint32_t _soff = (uint32_t)(_slot * NG * RSTAGE * ROW_BYTES);          \
        cp_async16(sdst0 + _soff, gsrc0 + _goff);                              \
        cp_async16(sdst1 + _soff, gsrc1 + _goff);                              \
    } while (0)

    // Prologue: stages 0..2 in flight before the mask barrier.
    ISSUE_STAGE(0); CP_COMMIT();
    ISSUE_STAGE(1); CP_COMMIT();
    ISSUE_STAGE(2); CP_COMMIT();

    __syncthreads();   // maskd ready for all

    // ---- Phase B: pipelined streaming ----
    unsigned long long acc0[9], acc1[9];   // <= 9 channels x (2 f32x2)
    #pragma unroll
    for (int k = 0; k < 9; ++k) { acc0[k] = 0ull; acc1[k] = 0ull; }

    const unsigned long long* mbase = maskd + (size_t)(ng * RPG2) * C_PAD;

    #pragma unroll 1
    for (int i = 0; i < STAGE_ITERS; ++i) {
        if (i + (S_STAGES - 1) < STAGE_ITERS) ISSUE_STAGE(i + (S_STAGES - 1));
        CP_COMMIT();                  // always commit: keeps group counting fixed
        CP_WAIT3();                   // own copies of stage i complete
        __syncthreads();              // everyone's copies of stage i complete

        const int slot = i & (S_STAGES - 1);
        const char* vs = pool + (size_t)((slot * NG + ng) * RSTAGE) * ROW_BYTES
                              + (size_t)q * 16;
        const unsigned long long* mrow0 = mbase + (size_t)(i * RSTAGE) * C_PAD;
        if (ch == 0) consume_stage<0, 8>(vs, mrow0, acc0, acc1);
        else         consume_stage<8, 9>(vs, mrow0, acc0, acc1);

        __syncthreads();              // all consumers done before slot reuse
    }

    // ---- Phase C1: reduce the 2 n-groups through shared memory ----
    float (*red)[D_DIM] = reinterpret_cast<float (*)[D_DIM]>(pool);
    #pragma unroll 1
    for (int gg = 0; gg < NG; ++gg) {
        if (ng == gg) {
            if (ch == 0) reduce_write<0, 8>(gg == 0, acc0, acc1, red, q);
            else         reduce_write<8, 9>(gg == 0, acc0, acc1, red, q);
        }
        __syncthreads();
    }

    // ---- Phase C2: scale + one atomic pass (256 threads cover D) ----
    const float scale = 1.0f / (float)N_DIM;
    float* op = out + (size_t)b * OUT_C * D_DIM + t;
    #pragma unroll
    for (int c = 0; c < OUT_C; ++c) {
        atomicAdd(op + c * D_DIM, red[c][t] * scale);
    }
}

extern "C" void kernel_launch(void* const* d_in, const int* in_sizes, int n_in,
                              void* d_out, int out_size) {
    // Inputs per metadata order: r_tensor (B*N*C), v_tensor (B*N*D).
    // Disambiguate defensively by element count.
    const float* r = (const float*)d_in[0];
    const float* v = (const float*)d_in[1];
    if (n_in >= 2 && in_sizes[0] == B_DIM * N_DIM * D_DIM &&
        in_sizes[1] == B_DIM * N_DIM * C_DIM) {
        r = (const float*)d_in[1];
        v = (const float*)d_in[0];
    }
    float* out = (float*)d_out;

    // Host-side attribute set (not a stream op; graph-capture safe, idempotent).
    cudaFuncSetAttribute(tf_fusion_kernel,
                         cudaFuncAttributeMaxDynamicSharedMemorySize, SMEM_TOTAL);

    const int out_elems = B_DIM * OUT_C * D_DIM;  // 139264
    tf_zero_kernel<<<(out_elems + 255) / 256, 256>>>(out, out_elems);

    dim3 grid(SPLIT, B_DIM);
    tf_fusion_kernel<<<grid, THREADS, SMEM_TOTAL>>>(r, v, out);
}